// round 16
// baseline (speedup 1.0000x reference)
#include <cuda_runtime.h>
#include <cstdint>

// LoRALayerNorm: y = ((x - mean) * rsqrt(var + eps)) * scale + shift
// x [2,4096,8192] fp32 -> 8192 rows of N=8192. scale/shift = 2 * rank-4 diag.
//
// R14: cp.async double-buffered row pipeline INSIDE the gap-free launch shape.
// Evidence: timed-vs-ncu gap is +2.5us for 24-warp/SM configs (3 CTA x 256t)
// and +12..14us for 32-warp configs, independent of load path. Best ncu so far
// (81.5us) came from cp.async pipelining but was only tested in 32-warp shapes.
// Here: TPB=256, grid=444, 64KB smem = 2x32KB row buffers (also forces exactly
// 3 CTAs/SM), tables via L1-resident __ldg, one barrier per row.

#define N_FEAT 8192
#define RANK   4
#define TPB    256
#define V4T    (N_FEAT / 4 / TPB)   // 8 float4 per thread
#define NWARPS (TPB / 32)           // 8
#define EPS_LN 1e-5f

__device__ float g_scale[N_FEAT];
__device__ float g_shift[N_FEAT];

__global__ void compute_scales_kernel(const float* __restrict__ sA,
                                      const float* __restrict__ sB,
                                      const float* __restrict__ hA,
                                      const float* __restrict__ hB) {
    int i = blockIdx.x * blockDim.x + threadIdx.x;
    if (i < N_FEAT) {
        float s = 0.f, h = 0.f;
#pragma unroll
        for (int r = 0; r < RANK; r++) {
            s = fmaf(sA[i * RANK + r], sB[r * N_FEAT + i], s);
            h = fmaf(hA[i * RANK + r], hB[r * N_FEAT + i], h);
        }
        g_scale[i] = s * 2.0f;   // SCALING = ALPHA/RANK = 8/4
        g_shift[i] = h * 2.0f;
    }
}

__device__ __forceinline__ void cp_async16(uint32_t smem_addr, const void* gptr) {
    asm volatile("cp.async.cg.shared.global [%0], [%1], 16;"
                 :: "r"(smem_addr), "l"(gptr) : "memory");
}
__device__ __forceinline__ void cp_async_commit() {
    asm volatile("cp.async.commit_group;" ::: "memory");
}
template <int N>
__device__ __forceinline__ void cp_async_wait() {
    asm volatile("cp.async.wait_group %0;" :: "n"(N) : "memory");
}

__global__ __launch_bounds__(TPB, 3)
void lora_ln_kernel(const float* __restrict__ x,
                    float* __restrict__ out,
                    int rows) {
    // dynamic smem: two 32KB row buffers (total 64KB -> exactly 3 CTAs/SM).
    extern __shared__ float4 s_buf[];              // [2][2048] float4
    __shared__ float2 red[2][NWARPS];              // parity double-buffered

    const uint32_t buf0 =
        (uint32_t)__cvta_generic_to_shared(s_buf) + (uint32_t)threadIdx.x * 16u;
    const uint32_t stage_stride = (uint32_t)(N_FEAT / 4) * 16u;   // 32KB

    const float4* gsc4 = reinterpret_cast<const float4*>(g_scale);
    const float4* gsh4 = reinterpret_cast<const float4*>(g_shift);

    const int lane = threadIdx.x & 31;
    const int warp = threadIdx.x >> 5;
    const float invN = 1.0f / (float)N_FEAT;

    int row = blockIdx.x;
    if (row >= rows) return;

    // Prologue: async-fetch first row into stage 0.
    {
        const float4* xr = reinterpret_cast<const float4*>(x + (size_t)row * N_FEAT);
#pragma unroll
        for (int j = 0; j < V4T; j++)
            cp_async16(buf0 + (uint32_t)(j * TPB) * 16u, xr + threadIdx.x + j * TPB);
        cp_async_commit();
    }

    int par = 0;
    for (; row < rows; row += gridDim.x, par ^= 1) {
        // Issue next row into the OTHER stage before touching this one.
        const int nrow = row + gridDim.x;
        if (nrow < rows) {
            const uint32_t dst = buf0 + (uint32_t)(par ^ 1) * stage_stride;
            const float4* xn = reinterpret_cast<const float4*>(x + (size_t)nrow * N_FEAT);
#pragma unroll
            for (int j = 0; j < V4T; j++)
                cp_async16(dst + (uint32_t)(j * TPB) * 16u, xn + threadIdx.x + j * TPB);
            cp_async_commit();
            cp_async_wait<1>();   // retire current row's group; next stays in flight
        } else {
            cp_async_wait<0>();
        }

        // Read current row (each thread reads only slots it wrote -> no barrier).
        const float4* cur = s_buf + par * (N_FEAT / 4);
        float4 v[V4T];
#pragma unroll
        for (int j = 0; j < V4T; j++)
            v[j] = cur[threadIdx.x + j * TPB];

        // Local accumulation.
        float sum = 0.f, sq = 0.f;
#pragma unroll
        for (int j = 0; j < V4T; j++) {
            sum += v[j].x + v[j].y + v[j].z + v[j].w;
            sq = fmaf(v[j].x, v[j].x, sq);
            sq = fmaf(v[j].y, v[j].y, sq);
            sq = fmaf(v[j].z, v[j].z, sq);
            sq = fmaf(v[j].w, v[j].w, sq);
        }

        // Warp reduction.
#pragma unroll
        for (int o = 16; o > 0; o >>= 1) {
            sum += __shfl_xor_sync(0xFFFFFFFFu, sum, o);
            sq  += __shfl_xor_sync(0xFFFFFFFFu, sq, o);
        }
        if (lane == 0) red[par][warp] = make_float2(sum, sq);
        __syncthreads();   // the ONLY barrier per row

        // Every warp redundantly reduces the 8 partials (parity buffer makes
        // the missing trailing barrier safe).
        float a = 0.f, b = 0.f;
        if (lane < NWARPS) { float2 t = red[par][lane]; a = t.x; b = t.y; }
#pragma unroll
        for (int o = NWARPS / 2; o > 0; o >>= 1) {
            a += __shfl_xor_sync(0xFFFFFFFFu, a, o);
            b += __shfl_xor_sync(0xFFFFFFFFu, b, o);
        }
        a = __shfl_sync(0xFFFFFFFFu, a, 0);
        b = __shfl_sync(0xFFFFFFFFu, b, 0);

        const float mean = a * invN;
        const float rstd = rsqrtf(fmaf(-mean, mean, b * invN) + EPS_LN);

        // Normalize + affine + streaming store. Table addresses are fixed per
        // thread across rows -> L1-resident after row 1 (cp.async.cg bypasses
        // L1 for x; __stcs streams out).
        float4* orw = reinterpret_cast<float4*>(out + (size_t)row * N_FEAT);
#pragma unroll
        for (int j = 0; j < V4T; j++) {
            const int i4 = threadIdx.x + j * TPB;
            const float4 sc = __ldg(&gsc4[i4]);
            const float4 sh = __ldg(&gsh4[i4]);
            float4 o;
            o.x = fmaf((v[j].x - mean) * rstd, sc.x, sh.x);
            o.y = fmaf((v[j].y - mean) * rstd, sc.y, sh.y);
            o.z = fmaf((v[j].z - mean) * rstd, sc.z, sh.z);
            o.w = fmaf((v[j].w - mean) * rstd, sc.w, sh.w);
            __stcs(&orw[i4], o);
        }
    }
}

extern "C" void kernel_launch(void* const* d_in, const int* in_sizes, int n_in,
                              void* d_out, int out_size) {
    const float* x  = (const float*)d_in[0];
    const float* sA = (const float*)d_in[1];
    const float* sB = (const float*)d_in[2];
    const float* hA = (const float*)d_in[3];
    const float* hB = (const float*)d_in[4];
    float* out = (float*)d_out;

    const int rows = in_sizes[0] / N_FEAT;           // 8192

    compute_scales_kernel<<<(N_FEAT + 255) / 256, 256>>>(sA, sB, hA, hB);

    const int smem_bytes = 2 * N_FEAT * sizeof(float);   // 64KB: 2 row buffers
    cudaFuncSetAttribute(lora_ln_kernel,
                         cudaFuncAttributeMaxDynamicSharedMemorySize, smem_bytes);

    int grid = 148 * 3;                                  // one wave, 3 CTAs/SM
    if (grid > rows) grid = rows;
    lora_ln_kernel<<<grid, TPB, smem_bytes>>>(x, out, rows);
}

// round 17
// speedup vs baseline: 1.0718x; 1.0718x over previous
#include <cuda_runtime.h>

// LoRALayerNorm: y = ((x - mean) * rsqrt(var + eps)) * scale + shift
// x [2,4096,8192] fp32 -> 8192 rows of N=8192. scale/shift = 2 * rank-4 diag.
//
// R16: R3 config verbatim (TPB=256, 3 CTAs/SM, grid=444, 64KB smem tables,
// __ldcs/__stcs) — the gap-free timed regime — with exactly ONE change:
// one barrier per row (parity-buffered partials + redundant per-warp block
// reduction) instead of R3's three. No prefetch (R13 showed it hurts).

#define N_FEAT 8192
#define RANK   4
#define TPB    256
#define V4T    (N_FEAT / 4 / TPB)   // 8 float4 per thread
#define NWARPS (TPB / 32)           // 8
#define EPS_LN 1e-5f

__device__ float g_scale[N_FEAT];
__device__ float g_shift[N_FEAT];

__global__ void compute_scales_kernel(const float* __restrict__ sA,
                                      const float* __restrict__ sB,
                                      const float* __restrict__ hA,
                                      const float* __restrict__ hB) {
    int i = blockIdx.x * blockDim.x + threadIdx.x;
    if (i < N_FEAT) {
        float s = 0.f, h = 0.f;
#pragma unroll
        for (int r = 0; r < RANK; r++) {
            s = fmaf(sA[i * RANK + r], sB[r * N_FEAT + i], s);
            h = fmaf(hA[i * RANK + r], hB[r * N_FEAT + i], h);
        }
        g_scale[i] = s * 2.0f;   // SCALING = ALPHA/RANK = 8/4
        g_shift[i] = h * 2.0f;
    }
}

__global__ __launch_bounds__(TPB, 3)
void lora_ln_kernel(const float* __restrict__ x,
                    float* __restrict__ out,
                    int rows) {
    extern __shared__ float4 smem4[];                 // 64 KB: scale + shift
    float4* s_scale = smem4;
    float4* s_shift = smem4 + N_FEAT / 4;
    __shared__ float2 red[2][NWARPS];                 // parity double-buffered

    // Load the per-feature affine vectors into shared once per CTA.
    const float4* gsc4 = reinterpret_cast<const float4*>(g_scale);
    const float4* gsh4 = reinterpret_cast<const float4*>(g_shift);
    for (int i = threadIdx.x; i < N_FEAT / 4; i += TPB) {
        s_scale[i] = gsc4[i];
        s_shift[i] = gsh4[i];
    }
    __syncthreads();

    const int lane = threadIdx.x & 31;
    const int warp = threadIdx.x >> 5;
    const float invN = 1.0f / (float)N_FEAT;

    int par = 0;
    for (int row = blockIdx.x; row < rows; row += gridDim.x, par ^= 1) {
        const float4* xr = reinterpret_cast<const float4*>(x + (size_t)row * N_FEAT);
        float4*       orw = reinterpret_cast<float4*>(out + (size_t)row * N_FEAT);

        // Front-batched streaming loads (MLP=8 per thread).
        float4 v[V4T];
#pragma unroll
        for (int j = 0; j < V4T; j++)
            v[j] = __ldcs(&xr[threadIdx.x + j * TPB]);

        float sum = 0.f, sq = 0.f;
#pragma unroll
        for (int j = 0; j < V4T; j++) {
            sum += v[j].x + v[j].y + v[j].z + v[j].w;
            sq = fmaf(v[j].x, v[j].x, sq);
            sq = fmaf(v[j].y, v[j].y, sq);
            sq = fmaf(v[j].z, v[j].z, sq);
            sq = fmaf(v[j].w, v[j].w, sq);
        }

        // Warp reduction.
#pragma unroll
        for (int o = 16; o > 0; o >>= 1) {
            sum += __shfl_xor_sync(0xFFFFFFFFu, sum, o);
            sq  += __shfl_xor_sync(0xFFFFFFFFu, sq, o);
        }
        if (lane == 0) red[par][warp] = make_float2(sum, sq);
        __syncthreads();   // the ONLY barrier per row

        // Every warp redundantly reduces the 8 partials (no broadcast barrier;
        // the parity buffer makes skipping the trailing barrier safe).
        float a = 0.f, b = 0.f;
        if (lane < NWARPS) { float2 t = red[par][lane]; a = t.x; b = t.y; }
#pragma unroll
        for (int o = NWARPS / 2; o > 0; o >>= 1) {
            a += __shfl_xor_sync(0xFFFFFFFFu, a, o);
            b += __shfl_xor_sync(0xFFFFFFFFu, b, o);
        }
        a = __shfl_sync(0xFFFFFFFFu, a, 0);
        b = __shfl_sync(0xFFFFFFFFu, b, 0);

        const float mean = a * invN;
        const float rstd = rsqrtf(fmaf(-mean, mean, b * invN) + EPS_LN);

        // Normalize + affine + streaming store (tables from smem).
#pragma unroll
        for (int j = 0; j < V4T; j++) {
            const int i4 = threadIdx.x + j * TPB;
            const float4 sc = s_scale[i4];
            const float4 sh = s_shift[i4];
            float4 o;
            o.x = fmaf((v[j].x - mean) * rstd, sc.x, sh.x);
            o.y = fmaf((v[j].y - mean) * rstd, sc.y, sh.y);
            o.z = fmaf((v[j].z - mean) * rstd, sc.z, sh.z);
            o.w = fmaf((v[j].w - mean) * rstd, sc.w, sh.w);
            __stcs(&orw[i4], o);
        }
    }
}

extern "C" void kernel_launch(void* const* d_in, const int* in_sizes, int n_in,
                              void* d_out, int out_size) {
    const float* x  = (const float*)d_in[0];
    const float* sA = (const float*)d_in[1];
    const float* sB = (const float*)d_in[2];
    const float* hA = (const float*)d_in[3];
    const float* hB = (const float*)d_in[4];
    float* out = (float*)d_out;

    const int rows = in_sizes[0] / N_FEAT;           // 8192

    compute_scales_kernel<<<(N_FEAT + 255) / 256, 256>>>(sA, sB, hA, hB);

    const int smem_bytes = 2 * N_FEAT * sizeof(float);   // 64 KB dynamic
    cudaFuncSetAttribute(lora_ln_kernel,
                         cudaFuncAttributeMaxDynamicSharedMemorySize, smem_bytes);

    int grid = 148 * 3;                                  // one wave, 3 CTAs/SM
    if (grid > rows) grid = rows;
    lora_ln_kernel<<<grid, TPB, smem_bytes>>>(x, out, rows);
}